// round 3
// baseline (speedup 1.0000x reference)
#include <cuda_runtime.h>
#include <math.h>

// Problem constants
#define kB  4
#define kS  2048
#define kD  1024
#define kH  16
#define kDK 64

static const size_t PROJ_ELEMS = (size_t)kB * kS * kD;        // 8388608
static const size_t ATTN_ELEMS = (size_t)kB * kH * kS * kS;   // 268435456

// Scratch (device globals — no runtime allocation allowed)
__device__ float g_Q[kB * kH * kS * kDK];      // [B*H, S, DK]
__device__ float g_K[kB * kH * kS * kDK];
__device__ float g_V[kB * kH * kS * kDK];
__device__ float g_comb[kB * kS * kD];         // [B, S, H*DK]
__device__ float g_proj[kB * kS * kD];         // fallback if d_out holds only attn
__device__ float g_attn[(size_t)kB * kH * kS * kS]; // fallback if d_out holds only proj

// ---------------------------------------------------------------------------
// NT GEMM: C[m,n] = sum_k A[m,k] * B[n,k]   (both row-major, K contiguous)
// BM=BN=128, BK=16, 256 threads, 8x8 per-thread microtile.
// MODE 0: plain row-major C [M,N]
// MODE 1: head-scatter for QKV projections: C laid out [B*H, S, DK]
// MODE 2: batched sim (blockIdx.z = b*H + h): scale by 0.125, apply mask,
//         C laid out [z, S, S]
// ---------------------------------------------------------------------------
template <int MODE>
__global__ void __launch_bounds__(256, 2)
gemm_nt_kernel(const float* __restrict__ A, const float* __restrict__ B,
               float* __restrict__ C, int M, int N, int K,
               const int* __restrict__ mask)
{
    __shared__ float As[16][132];
    __shared__ float Bs[16][132];

    if (MODE == 2) {
        int z = blockIdx.z;
        A += (size_t)z * kS * kDK;
        B += (size_t)z * kS * kDK;
        C += (size_t)z * kS * kS;
        mask += (size_t)(z / kH) * kS * kS;
    }

    const int tid  = threadIdx.x;
    const int tx   = tid & 15;
    const int ty   = tid >> 4;
    const int lrow = tid >> 2;          // 0..63
    const int lcol = (tid & 3) << 2;    // 0,4,8,12

    const int mBase = blockIdx.y * 128;
    const int nBase = blockIdx.x * 128;

    const float* Ap = A + (size_t)(mBase + lrow) * K + lcol;
    const float* Bp = B + (size_t)(nBase + lrow) * K + lcol;

    float acc[8][8];
#pragma unroll
    for (int i = 0; i < 8; i++)
#pragma unroll
        for (int j = 0; j < 8; j++) acc[i][j] = 0.0f;

    for (int k0 = 0; k0 < K; k0 += 16) {
        float4 a0 = *(const float4*)(Ap);
        float4 a1 = *(const float4*)(Ap + (size_t)64 * K);
        float4 b0 = *(const float4*)(Bp);
        float4 b1 = *(const float4*)(Bp + (size_t)64 * K);
        __syncthreads();   // protect smem from previous iteration's readers
        As[lcol + 0][lrow] = a0.x;  As[lcol + 1][lrow] = a0.y;
        As[lcol + 2][lrow] = a0.z;  As[lcol + 3][lrow] = a0.w;
        As[lcol + 0][lrow + 64] = a1.x;  As[lcol + 1][lrow + 64] = a1.y;
        As[lcol + 2][lrow + 64] = a1.z;  As[lcol + 3][lrow + 64] = a1.w;
        Bs[lcol + 0][lrow] = b0.x;  Bs[lcol + 1][lrow] = b0.y;
        Bs[lcol + 2][lrow] = b0.z;  Bs[lcol + 3][lrow] = b0.w;
        Bs[lcol + 0][lrow + 64] = b1.x;  Bs[lcol + 1][lrow + 64] = b1.y;
        Bs[lcol + 2][lrow + 64] = b1.z;  Bs[lcol + 3][lrow + 64] = b1.w;
        __syncthreads();

#pragma unroll
        for (int kk = 0; kk < 16; kk++) {
            float a[8], b[8];
            *(float4*)&a[0] = *(const float4*)&As[kk][ty * 8];
            *(float4*)&a[4] = *(const float4*)&As[kk][ty * 8 + 4];
            *(float4*)&b[0] = *(const float4*)&Bs[kk][tx * 8];
            *(float4*)&b[4] = *(const float4*)&Bs[kk][tx * 8 + 4];
#pragma unroll
            for (int i = 0; i < 8; i++)
#pragma unroll
                for (int j = 0; j < 8; j++)
                    acc[i][j] = fmaf(a[i], b[j], acc[i][j]);
        }
        Ap += 16;
        Bp += 16;
    }

#pragma unroll
    for (int i = 0; i < 8; i++) {
        const int m = mBase + ty * 8 + i;
#pragma unroll
        for (int j = 0; j < 8; j++) {
            const int n = nBase + tx * 8 + j;
            float v = acc[i][j];
            if (MODE == 0) {
                C[(size_t)m * N + n] = v;
            } else if (MODE == 1) {
                const int b  = m >> 11;          // m / kS
                const int s  = m & (kS - 1);
                const int h  = n >> 6;           // n / kDK
                const int dk = n & (kDK - 1);
                C[((size_t)(b * kH + h) * kS + s) * kDK + dk] = v;
            } else {
                v *= 0.125f;                     // 1/sqrt(DK)
                const int mv = mask[(size_t)m * kS + n];
                C[(size_t)m * kS + n] = mv ? v : -1e9f;
            }
        }
    }
}

// ---------------------------------------------------------------------------
// Row softmax over the last axis, in place. One block of 256 threads per row
// of 2048 elements; whole row lives in registers (8 floats/thread).
// ---------------------------------------------------------------------------
__global__ void __launch_bounds__(256)
softmax_kernel(float* __restrict__ attn)
{
    __shared__ float red[8];
    float* p = attn + (size_t)blockIdx.x * kS;
    const int t = threadIdx.x;

    float4 v0 = ((const float4*)p)[t];
    float4 v1 = ((const float4*)p)[t + 256];
    float vals[8] = {v0.x, v0.y, v0.z, v0.w, v1.x, v1.y, v1.z, v1.w};

    float m = vals[0];
#pragma unroll
    for (int i = 1; i < 8; i++) m = fmaxf(m, vals[i]);
#pragma unroll
    for (int o = 16; o > 0; o >>= 1) m = fmaxf(m, __shfl_xor_sync(0xffffffffu, m, o));
    if ((t & 31) == 0) red[t >> 5] = m;
    __syncthreads();
    float mb = red[0];
#pragma unroll
    for (int i = 1; i < 8; i++) mb = fmaxf(mb, red[i]);
    __syncthreads();   // everyone done reading red before reuse

    float s = 0.0f;
#pragma unroll
    for (int i = 0; i < 8; i++) {
        vals[i] = __expf(vals[i] - mb);
        s += vals[i];
    }
#pragma unroll
    for (int o = 16; o > 0; o >>= 1) s += __shfl_xor_sync(0xffffffffu, s, o);
    if ((t & 31) == 0) red[t >> 5] = s;
    __syncthreads();
    float tot = 0.0f;
#pragma unroll
    for (int i = 0; i < 8; i++) tot += red[i];
    const float inv = 1.0f / tot;

    ((float4*)p)[t]       = make_float4(vals[0] * inv, vals[1] * inv, vals[2] * inv, vals[3] * inv);
    ((float4*)p)[t + 256] = make_float4(vals[4] * inv, vals[5] * inv, vals[6] * inv, vals[7] * inv);
}

// ---------------------------------------------------------------------------
// PV GEMM (NN): per batch z = b*H + h:
//   scores[m, dk] = sum_k attn[z][m, k] * V[z][k, dk]
// written into combined layout [B, S, H*DK].
// BM=128, BN=64, BK=16, 256 threads, 8x4 microtile.
// ---------------------------------------------------------------------------
__global__ void __launch_bounds__(256, 2)
gemm_pv_kernel(const float* __restrict__ attn, const float* __restrict__ V,
               float* __restrict__ comb)
{
    __shared__ float As[16][132];
    __shared__ float Bs[16][68];

    const int z = blockIdx.z;
    const float* A  = attn + (size_t)z * kS * kS;
    const float* Bv = V + (size_t)z * kS * kDK;
    const int b = z / kH;
    const int h = z % kH;

    const int tid  = threadIdx.x;
    const int tx   = tid & 15;
    const int ty   = tid >> 4;
    const int lrow = tid >> 2;          // 0..63   (A tile loader)
    const int lcol = (tid & 3) << 2;
    const int brow = tid >> 4;          // 0..15   (B tile loader)
    const int bcol = (tid & 15) << 2;

    const int mBase = blockIdx.y * 128;
    const float* Ap = A + (size_t)(mBase + lrow) * kS + lcol;
    const float* Bp = Bv + (size_t)brow * kDK + bcol;

    float acc[8][4];
#pragma unroll
    for (int i = 0; i < 8; i++)
#pragma unroll
        for (int j = 0; j < 4; j++) acc[i][j] = 0.0f;

    for (int k0 = 0; k0 < kS; k0 += 16) {
        float4 a0 = *(const float4*)(Ap);
        float4 a1 = *(const float4*)(Ap + (size_t)64 * kS);
        float4 bb = *(const float4*)(Bp);
        __syncthreads();
        As[lcol + 0][lrow] = a0.x;  As[lcol + 1][lrow] = a0.y;
        As[lcol + 2][lrow] = a0.z;  As[lcol + 3][lrow] = a0.w;
        As[lcol + 0][lrow + 64] = a1.x;  As[lcol + 1][lrow + 64] = a1.y;
        As[lcol + 2][lrow + 64] = a1.z;  As[lcol + 3][lrow + 64] = a1.w;
        *(float4*)&Bs[brow][bcol] = bb;
        __syncthreads();

#pragma unroll
        for (int kk = 0; kk < 16; kk++) {
            float a[8], c[4];
            *(float4*)&a[0] = *(const float4*)&As[kk][ty * 8];
            *(float4*)&a[4] = *(const float4*)&As[kk][ty * 8 + 4];
            *(float4*)&c[0] = *(const float4*)&Bs[kk][tx * 4];
#pragma unroll
            for (int i = 0; i < 8; i++)
#pragma unroll
                for (int j = 0; j < 4; j++)
                    acc[i][j] = fmaf(a[i], c[j], acc[i][j]);
        }
        Ap += 16;
        Bp += (size_t)16 * kDK;
    }

#pragma unroll
    for (int i = 0; i < 8; i++) {
        const int s = mBase + ty * 8 + i;
#pragma unroll
        for (int j = 0; j < 4; j++) {
            const int dk = tx * 4 + j;
            comb[(size_t)(b * kS + s) * kD + h * kDK + dk] = acc[i][j];
        }
    }
}

// ---------------------------------------------------------------------------
extern "C" void kernel_launch(void* const* d_in, const int* in_sizes, int n_in,
                              void* d_out, int out_size)
{
    const float* q    = (const float*)d_in[0];
    const float* k    = (const float*)d_in[1];
    const float* v    = (const float*)d_in[2];
    const int*   mask = (const int*)d_in[3];
    const float* Wq   = (const float*)d_in[4];
    const float* Wk   = (const float*)d_in[5];
    const float* Wv   = (const float*)d_in[6];
    const float* Wo   = (const float*)d_in[7];
    float* out = (float*)d_out;

    float *gQ, *gK, *gV, *gC, *gA, *gP;
    cudaGetSymbolAddress((void**)&gQ, g_Q);
    cudaGetSymbolAddress((void**)&gK, g_K);
    cudaGetSymbolAddress((void**)&gV, g_V);
    cudaGetSymbolAddress((void**)&gC, g_comb);
    cudaGetSymbolAddress((void**)&gA, g_attn);
    cudaGetSymbolAddress((void**)&gP, g_proj);

    // Output layout: expect (projected, attn) concatenated; fall back sanely.
    const size_t osz = (size_t)out_size;
    float* projPtr;
    float* attnPtr;
    if (osz >= PROJ_ELEMS + ATTN_ELEMS) {
        projPtr = out;
        attnPtr = out + PROJ_ELEMS;
    } else if (osz >= ATTN_ELEMS) {   // attn only
        projPtr = gP;
        attnPtr = out;
    } else {                           // projected only
        projPtr = out;
        attnPtr = gA;
    }

    const dim3 blk(256);
    const int MROWS = kB * kS;        // 8192

    // QKV projections (NT gemm, head-scatter epilogue)
    gemm_nt_kernel<1><<<dim3(kD / 128, MROWS / 128, 1), blk>>>(q, Wq, gQ, MROWS, kD, kD, nullptr);
    gemm_nt_kernel<1><<<dim3(kD / 128, MROWS / 128, 1), blk>>>(k, Wk, gK, MROWS, kD, kD, nullptr);
    gemm_nt_kernel<1><<<dim3(kD / 128, MROWS / 128, 1), blk>>>(v, Wv, gV, MROWS, kD, kD, nullptr);

    // sim = Q K^T / sqrt(DK), masked  (batched over B*H)
    gemm_nt_kernel<2><<<dim3(kS / 128, kS / 128, kB * kH), blk>>>(gQ, gK, attnPtr, kS, kS, kDK, mask);

    // softmax in place (this is the attn output)
    softmax_kernel<<<kB * kH * kS, 256>>>(attnPtr);

    // scores = attn @ V  -> combined [B,S,D]
    gemm_pv_kernel<<<dim3(1, kS / 128, kB * kH), blk>>>(attnPtr, gV, gC);

    // projected = combined @ Wo^T
    gemm_nt_kernel<0><<<dim3(kD / 128, MROWS / 128, 1), blk>>>(gC, Wo, projPtr, MROWS, kD, kD, nullptr);
}

// round 5
// speedup vs baseline: 1.7270x; 1.7270x over previous
#include <cuda_runtime.h>
#include <cuda_bf16.h>
#include <stdint.h>
#include <math.h>

// Problem constants
#define kB  4
#define kS  2048
#define kD  1024
#define kH  16
#define kDK 64

static const size_t PROJ_ELEMS = (size_t)kB * kS * kD;        // 8388608
static const size_t ATTN_ELEMS = (size_t)kB * kH * kS * kS;   // 268435456

// Scratch (device globals — no runtime allocation allowed)
__device__ float g_Q[kB * kH * kS * kDK];      // [B*H, S, DK]
__device__ float g_K[kB * kH * kS * kDK];      // [B*H, S, DK]
__device__ float g_Vt[kB * kH * kDK * kS];     // [B*H, DK, S]  (transposed V)
__device__ float g_comb[kB * kS * kD];         // [B, S, H*DK]
__device__ float g_proj[kB * kS * kD];         // fallback
__device__ float g_attn[(size_t)kB * kH * kS * kS]; // fallback

// ---------------------------------------------------------------------------
// split-bf16 helpers:  f = hi + lo  (bf16 each), packed in pairs (bf16x2)
// ---------------------------------------------------------------------------
__device__ __forceinline__ uint32_t pack_split(float f0, float f1, uint32_t& lo)
{
    __nv_bfloat162 h = __floats2bfloat162_rn(f0, f1);
    float r0 = f0 - __bfloat162float(h.x);
    float r1 = f1 - __bfloat162float(h.y);
    __nv_bfloat162 l = __floats2bfloat162_rn(r0, r1);
    lo = *reinterpret_cast<uint32_t*>(&l);
    return *reinterpret_cast<uint32_t*>(&h);
}

__device__ __forceinline__ void mma16816(float* c, const uint32_t* a,
                                         uint32_t b0, uint32_t b1)
{
    asm volatile(
        "mma.sync.aligned.m16n8k16.row.col.f32.bf16.bf16.f32 "
        "{%0,%1,%2,%3}, {%4,%5,%6,%7}, {%8,%9}, {%0,%1,%2,%3};\n"
        : "+f"(c[0]), "+f"(c[1]), "+f"(c[2]), "+f"(c[3])
        : "r"(a[0]), "r"(a[1]), "r"(a[2]), "r"(a[3]), "r"(b0), "r"(b1));
}

// ---------------------------------------------------------------------------
// Split-bf16 NT GEMM: C[m,n] = sum_k A[m,k]*B[n,k], fp32 in/out, 3-term mma.
// BM=128, BN=NTILES*32, BK=32. 256 threads = 8 warps (2 M x 4 N), warp tile
// 64 x NTILES*8.  MODEs:
//   0: C row-major [M,N]
//   1: QK proj scatter: C = [B*H][S][DK]
//   2: batched sim (z=b*H+h): *0.125, mask, C=[z][S][S]
//   3: V proj transposed scatter: C = [B*H][DK][S]
//   4: batched PV (z): C -> comb [B][S][H*DK]
// ---------------------------------------------------------------------------
template <int MODE, int NTILES>
__global__ void __launch_bounds__(256)
gemm_bf16s_kernel(const float* __restrict__ A, const float* __restrict__ B,
                  float* __restrict__ C, int M_, int N_, int K,
                  const int* __restrict__ mask)
{
    __shared__ uint32_t sAh[128][20], sAl[128][20];
    __shared__ uint32_t sBh[128][20], sBl[128][20];

    constexpr int BN = NTILES * 32;
    constexpr int WN = NTILES * 8;

    const int z = blockIdx.z;
    if (MODE == 2) {
        A += (size_t)z * kS * kDK;
        B += (size_t)z * kS * kDK;
        C += (size_t)z * kS * kS;
        mask += (size_t)(z >> 4) * kS * kS;
    }
    if (MODE == 4) {
        A += (size_t)z * kS * kS;      // attn
        B += (size_t)z * kDK * kS;     // Vt
    }

    const int t    = threadIdx.x;
    const int lane = t & 31;
    const int wid  = t >> 5;
    const int gid  = lane >> 2;
    const int tig  = lane & 3;
    const int warpM = wid & 1;
    const int warpN = wid >> 1;
    const int mBase = blockIdx.y * 128;
    const int nBase = blockIdx.x * BN;

    const int  lrow = t >> 1;
    const int  lseg = t & 1;
    const bool bval = (lrow < BN);
    const float* Ald = A + (size_t)(mBase + lrow) * K + lseg * 16;
    const float* Bld = B + (size_t)(nBase + (bval ? lrow : 0)) * K + lseg * 16;

    float acc[4][NTILES][4];
#pragma unroll
    for (int i = 0; i < 4; i++)
#pragma unroll
        for (int j = 0; j < NTILES; j++)
#pragma unroll
            for (int r = 0; r < 4; r++) acc[i][j][r] = 0.0f;

    // prefetch first tile into registers
    float4 pa[4], pb[4];
#pragma unroll
    for (int u = 0; u < 4; u++) pa[u] = *(const float4*)(Ald + u * 4);
    if (bval)
#pragma unroll
        for (int u = 0; u < 4; u++) pb[u] = *(const float4*)(Bld + u * 4);

    for (int k0 = 0; k0 < K; k0 += 32) {
        __syncthreads();   // previous iteration's readers done
        {
            uint32_t hw[8], lw[8];
#pragma unroll
            for (int u = 0; u < 4; u++) {
                hw[2*u+0] = pack_split(pa[u].x, pa[u].y, lw[2*u+0]);
                hw[2*u+1] = pack_split(pa[u].z, pa[u].w, lw[2*u+1]);
            }
            *(uint4*)&sAh[lrow][lseg*8]     = make_uint4(hw[0], hw[1], hw[2], hw[3]);
            *(uint4*)&sAh[lrow][lseg*8 + 4] = make_uint4(hw[4], hw[5], hw[6], hw[7]);
            *(uint4*)&sAl[lrow][lseg*8]     = make_uint4(lw[0], lw[1], lw[2], lw[3]);
            *(uint4*)&sAl[lrow][lseg*8 + 4] = make_uint4(lw[4], lw[5], lw[6], lw[7]);
            if (bval) {
#pragma unroll
                for (int u = 0; u < 4; u++) {
                    hw[2*u+0] = pack_split(pb[u].x, pb[u].y, lw[2*u+0]);
                    hw[2*u+1] = pack_split(pb[u].z, pb[u].w, lw[2*u+1]);
                }
                *(uint4*)&sBh[lrow][lseg*8]     = make_uint4(hw[0], hw[1], hw[2], hw[3]);
                *(uint4*)&sBh[lrow][lseg*8 + 4] = make_uint4(hw[4], hw[5], hw[6], hw[7]);
                *(uint4*)&sBl[lrow][lseg*8]     = make_uint4(lw[0], lw[1], lw[2], lw[3]);
                *(uint4*)&sBl[lrow][lseg*8 + 4] = make_uint4(lw[4], lw[5], lw[6], lw[7]);
            }
        }
        __syncthreads();

        if (k0 + 32 < K) {   // prefetch next tile (overlaps with mma below)
            Ald += 32; Bld += 32;
#pragma unroll
            for (int u = 0; u < 4; u++) pa[u] = *(const float4*)(Ald + u * 4);
            if (bval)
#pragma unroll
                for (int u = 0; u < 4; u++) pb[u] = *(const float4*)(Bld + u * 4);
        }

#pragma unroll
        for (int s = 0; s < 2; s++) {
            const int kp = s * 8 + tig;
            uint32_t ah[4][4], al[4][4];
#pragma unroll
            for (int i = 0; i < 4; i++) {
                const int r = warpM * 64 + i * 16 + gid;
                ah[i][0] = sAh[r][kp];       ah[i][1] = sAh[r + 8][kp];
                ah[i][2] = sAh[r][kp + 4];   ah[i][3] = sAh[r + 8][kp + 4];
                al[i][0] = sAl[r][kp];       al[i][1] = sAl[r + 8][kp];
                al[i][2] = sAl[r][kp + 4];   al[i][3] = sAl[r + 8][kp + 4];
            }
#pragma unroll
            for (int j = 0; j < NTILES; j++) {
                const int n = warpN * WN + j * 8 + gid;
                const uint32_t bh0 = sBh[n][kp], bh1 = sBh[n][kp + 4];
                const uint32_t bl0 = sBl[n][kp], bl1 = sBl[n][kp + 4];
#pragma unroll
                for (int i = 0; i < 4; i++) {
                    mma16816(acc[i][j], ah[i], bh0, bh1);   // hi*hi
                    mma16816(acc[i][j], al[i], bh0, bh1);   // lo*hi
                    mma16816(acc[i][j], ah[i], bl0, bl1);   // hi*lo
                }
            }
        }
    }

    // ---------------- epilogue ----------------
#pragma unroll
    for (int i = 0; i < 4; i++) {
        const int m0 = mBase + warpM * 64 + i * 16 + gid;   // and m0+8
#pragma unroll
        for (int j = 0; j < NTILES; j++) {
            const int n = nBase + warpN * WN + j * 8 + tig * 2;   // and n+1
            const float c0 = acc[i][j][0], c1 = acc[i][j][1];
            const float c2 = acc[i][j][2], c3 = acc[i][j][3];

            if (MODE == 0) {
                *(float2*)&C[(size_t)m0 * N_ + n]       = make_float2(c0, c1);
                *(float2*)&C[(size_t)(m0 + 8) * N_ + n] = make_float2(c2, c3);
            } else if (MODE == 2) {
                const int2 ma = *(const int2*)&mask[(size_t)m0 * kS + n];
                const int2 mb = *(const int2*)&mask[(size_t)(m0 + 8) * kS + n];
                *(float2*)&C[(size_t)m0 * kS + n] =
                    make_float2(ma.x ? c0 * 0.125f : -1e9f,
                                ma.y ? c1 * 0.125f : -1e9f);
                *(float2*)&C[(size_t)(m0 + 8) * kS + n] =
                    make_float2(mb.x ? c2 * 0.125f : -1e9f,
                                mb.y ? c3 * 0.125f : -1e9f);
            } else if (MODE == 1) {
                const int b = m0 >> 11, s0 = m0 & (kS - 1);
                const int h = n >> 6,  dk = n & (kDK - 1);
                const size_t base = (size_t)(b * kH + h) * kS;
                *(float2*)&C[(base + s0) * kDK + dk]     = make_float2(c0, c1);
                *(float2*)&C[(base + s0 + 8) * kDK + dk] = make_float2(c2, c3);
            } else if (MODE == 3) {
                const int b = m0 >> 11, s0 = m0 & (kS - 1);
                const int h = n >> 6,  dk = n & (kDK - 1);
                const size_t base = ((size_t)(b * kH + h) * kDK + dk) * kS;
                C[base + s0]          = c0;
                C[base + kS + s0]     = c1;
                C[base + s0 + 8]      = c2;
                C[base + kS + s0 + 8] = c3;
            } else if (MODE == 4) {
                const int b = z >> 4, h = z & 15;
                const size_t r0 = ((size_t)b * kS + m0) * kD + h * kDK + n;
                *(float2*)&C[r0]           = make_float2(c0, c1);
                *(float2*)&C[r0 + 8 * kD]  = make_float2(c2, c3);
            }
        }
    }
}

// ---------------------------------------------------------------------------
// Row softmax over the last axis, in place. One block per 2048-element row.
// ---------------------------------------------------------------------------
__global__ void __launch_bounds__(256)
softmax_kernel(float* __restrict__ attn)
{
    __shared__ float red[8];
    float* p = attn + (size_t)blockIdx.x * kS;
    const int t = threadIdx.x;

    float4 v0 = ((const float4*)p)[t];
    float4 v1 = ((const float4*)p)[t + 256];
    float vals[8] = {v0.x, v0.y, v0.z, v0.w, v1.x, v1.y, v1.z, v1.w};

    float m = vals[0];
#pragma unroll
    for (int i = 1; i < 8; i++) m = fmaxf(m, vals[i]);
#pragma unroll
    for (int o = 16; o > 0; o >>= 1) m = fmaxf(m, __shfl_xor_sync(0xffffffffu, m, o));
    if ((t & 31) == 0) red[t >> 5] = m;
    __syncthreads();
    float mb = red[0];
#pragma unroll
    for (int i = 1; i < 8; i++) mb = fmaxf(mb, red[i]);
    __syncthreads();

    float s = 0.0f;
#pragma unroll
    for (int i = 0; i < 8; i++) {
        vals[i] = __expf(vals[i] - mb);
        s += vals[i];
    }
#pragma unroll
    for (int o = 16; o > 0; o >>= 1) s += __shfl_xor_sync(0xffffffffu, s, o);
    if ((t & 31) == 0) red[t >> 5] = s;
    __syncthreads();
    float tot = 0.0f;
#pragma unroll
    for (int i = 0; i < 8; i++) tot += red[i];
    const float inv = 1.0f / tot;

    ((float4*)p)[t]       = make_float4(vals[0]*inv, vals[1]*inv, vals[2]*inv, vals[3]*inv);
    ((float4*)p)[t + 256] = make_float4(vals[4]*inv, vals[5]*inv, vals[6]*inv, vals[7]*inv);
}

// ---------------------------------------------------------------------------
extern "C" void kernel_launch(void* const* d_in, const int* in_sizes, int n_in,
                              void* d_out, int out_size)
{
    const float* q    = (const float*)d_in[0];
    const float* k    = (const float*)d_in[1];
    const float* v    = (const float*)d_in[2];
    const int*   mask = (const int*)d_in[3];
    const float* Wq   = (const float*)d_in[4];
    const float* Wk   = (const float*)d_in[5];
    const float* Wv   = (const float*)d_in[6];
    const float* Wo   = (const float*)d_in[7];
    float* out = (float*)d_out;

    float *gQ, *gK, *gVt, *gC, *gA, *gP;
    cudaGetSymbolAddress((void**)&gQ,  g_Q);
    cudaGetSymbolAddress((void**)&gK,  g_K);
    cudaGetSymbolAddress((void**)&gVt, g_Vt);
    cudaGetSymbolAddress((void**)&gC,  g_comb);
    cudaGetSymbolAddress((void**)&gA,  g_attn);
    cudaGetSymbolAddress((void**)&gP,  g_proj);

    const size_t osz = (size_t)out_size;
    float* projPtr;
    float* attnPtr;
    if (osz >= PROJ_ELEMS + ATTN_ELEMS) {
        projPtr = out;
        attnPtr = out + PROJ_ELEMS;
    } else if (osz >= ATTN_ELEMS) {
        projPtr = gP;
        attnPtr = out;
    } else {
        projPtr = out;
        attnPtr = gA;
    }

    const dim3 blk(256);
    const int MROWS = kB * kS;   // 8192

    // QKV projections (split-bf16 mma, head-scatter / transpose epilogues)
    gemm_bf16s_kernel<1,4><<<dim3(kD/128, MROWS/128, 1), blk>>>(q, Wq, gQ,  MROWS, kD, kD, nullptr);
    gemm_bf16s_kernel<1,4><<<dim3(kD/128, MROWS/128, 1), blk>>>(k, Wk, gK,  MROWS, kD, kD, nullptr);
    gemm_bf16s_kernel<3,4><<<dim3(kD/128, MROWS/128, 1), blk>>>(v, Wv, gVt, MROWS, kD, kD, nullptr);

    // sim = Q K^T / 8, masked  (batched over B*H)
    gemm_bf16s_kernel<2,4><<<dim3(kS/128, kS/128, kB*kH), blk>>>(gQ, gK, attnPtr, kS, kS, kDK, mask);

    // softmax in place (this is the attn output)
    softmax_kernel<<<kB*kH*kS, 256>>>(attnPtr);

    // scores = attn @ V  -> combined [B,S,D]   (NT against transposed V)
    gemm_bf16s_kernel<4,2><<<dim3(1, kS/128, kB*kH), blk>>>(attnPtr, gVt, gC, kS, kDK, kS, nullptr);

    // projected = combined @ Wo^T
    gemm_bf16s_kernel<0,4><<<dim3(kD/128, MROWS/128, 1), blk>>>(gC, Wo, projPtr, MROWS, kD, kD, nullptr);
}